// round 2
// baseline (speedup 1.0000x reference)
#include <cuda_runtime.h>
#include <cuda_bf16.h>
#include <math.h>

#define B_SZ 2
#define NTOK 2048
#define NH 8
#define DK 64
#define DM 512

// Scratch (device globals; no cudaMalloc allowed)
__device__ float g_qh[B_SZ * NH * NTOK * DK];   // [b][h][n][dk], pre-scaled by 1/sqrt(dk)
__device__ float g_kh[B_SZ * NH * NTOK * DK];
__device__ float g_vh[B_SZ * NH * NTOK * DK];
__device__ float g_o [B_SZ * NTOK * DM];        // [b][n][h*64+dk]

#define INF_F __int_as_float(0x7f800000)

// ---------------------------------------------------------------------------
// Projection GEMM: for z in {q,k,v}: out[b,h,n,:] = X[b,n,:] @ proj[h]  (X:[4096,512])
// 64x64 tiles, K chunks of 32, 256 threads, 4x4 register tiles.
// ---------------------------------------------------------------------------
__global__ __launch_bounds__(256) void proj_kernel(
    const float* __restrict__ q, const float* __restrict__ k, const float* __restrict__ v,
    const float* __restrict__ qp, const float* __restrict__ kpj, const float* __restrict__ vp)
{
    __shared__ float AsT[32 * 68];   // [kk][row]
    __shared__ float Bs [32 * 68];   // [kk][col]

    const int tid = threadIdx.x;
    const int tx = tid & 15, ty = tid >> 4;
    const int h  = blockIdx.x;          // column tile == head (64-wide)
    const int r0 = blockIdx.y * 64;     // row tile into [4096]
    const int z  = blockIdx.z;

    const float* X = (z == 0) ? q : (z == 1) ? k : v;
    const float* W = (z == 0) ? qp : (z == 1) ? kpj : vp;

    float acc[4][4];
#pragma unroll
    for (int i = 0; i < 4; i++)
#pragma unroll
        for (int j = 0; j < 4; j++) acc[i][j] = 0.f;

    for (int k0 = 0; k0 < DM; k0 += 32) {
        // load A tile transposed: X[(r0+r)][k0+kk] -> AsT[kk][r]
        {
            int r = tid >> 2, j = tid & 3;
            const float4* asrc = (const float4*)(X + (size_t)(r0 + r) * DM + k0 + j * 8);
#pragma unroll
            for (int p = 0; p < 2; p++) {
                float4 a4 = asrc[p];
                int d = j * 8 + p * 4;
                AsT[(d + 0) * 68 + r] = a4.x;
                AsT[(d + 1) * 68 + r] = a4.y;
                AsT[(d + 2) * 68 + r] = a4.z;
                AsT[(d + 3) * 68 + r] = a4.w;
            }
        }
        // load B tile natural: proj[h][(k0+kk)][cc] -> Bs[kk][cc]
        {
            int kk = tid >> 3, jj = tid & 7;
            const float4* bsrc = (const float4*)(W + (size_t)h * DM * DK + (size_t)(k0 + kk) * DK + jj * 8);
            *(float4*)(Bs + kk * 68 + jj * 8)     = bsrc[0];
            *(float4*)(Bs + kk * 68 + jj * 8 + 4) = bsrc[1];
        }
        __syncthreads();
#pragma unroll
        for (int kk = 0; kk < 32; kk++) {
            float4 a = *(const float4*)(AsT + kk * 68 + 4 * ty);
            float4 b = *(const float4*)(Bs  + kk * 68 + 4 * tx);
            acc[0][0] += a.x * b.x; acc[0][1] += a.x * b.y; acc[0][2] += a.x * b.z; acc[0][3] += a.x * b.w;
            acc[1][0] += a.y * b.x; acc[1][1] += a.y * b.y; acc[1][2] += a.y * b.z; acc[1][3] += a.y * b.w;
            acc[2][0] += a.z * b.x; acc[2][1] += a.z * b.y; acc[2][2] += a.z * b.z; acc[2][3] += a.z * b.w;
            acc[3][0] += a.w * b.x; acc[3][1] += a.w * b.y; acc[3][2] += a.w * b.z; acc[3][3] += a.w * b.w;
        }
        __syncthreads();
    }

    const float scale = (z == 0) ? 0.125f : 1.0f;   // 1/sqrt(64) folded into Q
    float* dst = (z == 0) ? g_qh : (z == 1) ? g_kh : g_vh;
#pragma unroll
    for (int i = 0; i < 4; i++) {
        int row = r0 + 4 * ty + i;
        int bb = row >> 11, n = row & (NTOK - 1);
        float4 o = make_float4(acc[i][0] * scale, acc[i][1] * scale, acc[i][2] * scale, acc[i][3] * scale);
        *(float4*)(dst + (((size_t)bb * NH + h) * NTOK + n) * DK + 4 * tx) = o;
    }
}

// ---------------------------------------------------------------------------
// Fused distance-modulated flash attention.
// One block per (q-tile 64, h, b). 256 threads, 4x4 register tiles.
// ---------------------------------------------------------------------------
__global__ __launch_bounds__(256, 2) void attn_kernel(
    const float* __restrict__ coords, const unsigned char* __restrict__ kpm)
{
    extern __shared__ float sm[];
    float* qsT = sm;               // [64 dim][68]  (transposed, [d][row])
    float* ksT = sm + 4352;        // [64 dim][68]  (transposed, [d][col])
    float* vs  = sm + 8704;        // [64 m][68]    (natural)
    float* ps  = sm + 13056;       // [64 r][68]    (natural)
    float* mc  = sm + 17408;       // [64*3] m-coords
    float* kpf = sm + 17600;       // [64] key-padding flags

    const int tid = threadIdx.x;
    const int tx = tid & 15, ty = tid >> 4;
    const int b = blockIdx.z, h = blockIdx.y;
    const int q0 = blockIdx.x * 64;

    // head spread constants
    const float tpow   = 0.98f * (float)h / 7.0f;
    const float spread = 3.7f + (powf(20.0f, tpow) - 1.0f) * (16.3f / 19.0f);
    const float s2      = spread * spread;
    const float nine_s2 = 9.0f * s2;
    const float inv2s2  = 1.0f / (2.0f * s2);

    const float* qbase = g_qh + (((size_t)b * NH + h) * NTOK + q0) * DK;
    const float* kbase = g_kh + (((size_t)b * NH + h) * NTOK) * DK;
    const float* vbase = g_vh + (((size_t)b * NH + h) * NTOK) * DK;

    // load Q tile transposed (once)
    {
        int r = tid >> 2, j = tid & 3;
        const float4* src = (const float4*)(qbase + r * DK + j * 16);
#pragma unroll
        for (int p = 0; p < 4; p++) {
            float4 a4 = src[p];
            int d = j * 16 + p * 4;
            qsT[(d + 0) * 68 + r] = a4.x;
            qsT[(d + 1) * 68 + r] = a4.y;
            qsT[(d + 2) * 68 + r] = a4.z;
            qsT[(d + 3) * 68 + r] = a4.w;
        }
    }
    // q coords for my 4 rows (registers)
    float qcx[4], qcy[4], qcz[4];
#pragma unroll
    for (int i = 0; i < 4; i++) {
        const float* cp = coords + ((size_t)b * NTOK + q0 + 4 * ty + i) * 3;
        qcx[i] = cp[0]; qcy[i] = cp[1]; qcz[i] = cp[2];
    }

    float mI[4], lI[4], accO[4][4];
#pragma unroll
    for (int i = 0; i < 4; i++) {
        mI[i] = -INF_F; lI[i] = 0.f;
#pragma unroll
        for (int j = 0; j < 4; j++) accO[i][j] = 0.f;
    }

    for (int mt = 0; mt < NTOK / 64; mt++) {
        const int m0 = mt * 64;
        // --- loads ---
        {
            int r = tid >> 2, j = tid & 3;
            const float4* ksrc = (const float4*)(kbase + (size_t)(m0 + r) * DK + j * 16);
#pragma unroll
            for (int p = 0; p < 4; p++) {
                float4 a4 = ksrc[p];
                int d = j * 16 + p * 4;
                ksT[(d + 0) * 68 + r] = a4.x;
                ksT[(d + 1) * 68 + r] = a4.y;
                ksT[(d + 2) * 68 + r] = a4.z;
                ksT[(d + 3) * 68 + r] = a4.w;
            }
            const float4* vsrc = (const float4*)(vbase + (size_t)(m0 + r) * DK + j * 16);
            float4* vdst = (float4*)(vs + r * 68 + j * 16);
#pragma unroll
            for (int p = 0; p < 4; p++) vdst[p] = vsrc[p];
        }
        if (tid < 64) {
            const float* cp = coords + ((size_t)b * NTOK + m0 + tid) * 3;
            mc[tid * 3 + 0] = cp[0];
            mc[tid * 3 + 1] = cp[1];
            mc[tid * 3 + 2] = cp[2];
            kpf[tid] = kpm[(size_t)b * NTOK + m0 + tid] ? 1.f : 0.f;
        }
        __syncthreads();

        // --- S = Q Kt (scaled logits; scale already folded into Q) ---
        float acc[4][4];
#pragma unroll
        for (int i = 0; i < 4; i++)
#pragma unroll
            for (int j = 0; j < 4; j++) acc[i][j] = 0.f;
#pragma unroll 4
        for (int kk = 0; kk < DK; kk++) {
            float4 a = *(const float4*)(qsT + kk * 68 + 4 * ty);
            float4 bb = *(const float4*)(ksT + kk * 68 + 4 * tx);
            acc[0][0] += a.x * bb.x; acc[0][1] += a.x * bb.y; acc[0][2] += a.x * bb.z; acc[0][3] += a.x * bb.w;
            acc[1][0] += a.y * bb.x; acc[1][1] += a.y * bb.y; acc[1][2] += a.y * bb.z; acc[1][3] += a.y * bb.w;
            acc[2][0] += a.z * bb.x; acc[2][1] += a.z * bb.y; acc[2][2] += a.z * bb.z; acc[2][3] += a.z * bb.w;
            acc[3][0] += a.w * bb.x; acc[3][1] += a.w * bb.y; acc[3][2] += a.w * bb.z; acc[3][3] += a.w * bb.w;
        }

        // --- RBF modulation + online softmax partial ---
#pragma unroll
        for (int i = 0; i < 4; i++) {
            float sv[4];
            float rm = -INF_F;
#pragma unroll
            for (int j = 0; j < 4; j++) {
                int c = 4 * tx + j;
                float dx = qcx[i] - mc[c * 3 + 0];
                float dy = qcy[i] - mc[c * 3 + 1];
                float dz = qcz[i] - mc[c * 3 + 2];
                float d2 = dx * dx + dy * dy + dz * dz;
                float s = acc[i][j];
                float arg = fmaxf(d2, s2) * inv2s2;           // in [0.5, 4.5] when unmasked
                float mod = s * __expf(copysignf(arg, -s));   // s<0 -> *exp(+arg), else *exp(-arg)
                bool masked = (kpf[c] != 0.f) || (d2 > nine_s2);
                sv[j] = masked ? -INF_F : mod;
                rm = fmaxf(rm, sv[j]);
            }
            // row max across 16 lanes
            rm = fmaxf(rm, __shfl_xor_sync(0xffffffffu, rm, 1));
            rm = fmaxf(rm, __shfl_xor_sync(0xffffffffu, rm, 2));
            rm = fmaxf(rm, __shfl_xor_sync(0xffffffffu, rm, 4));
            rm = fmaxf(rm, __shfl_xor_sync(0xffffffffu, rm, 8));
            float nm = fmaxf(mI[i], rm);
            float cf, psum = 0.f;
            if (nm == -INF_F) {          // fully masked so far
                cf = 1.f;
#pragma unroll
                for (int j = 0; j < 4; j++) sv[j] = 0.f;
            } else {
                cf = __expf(mI[i] - nm); // mI = -inf -> 0
#pragma unroll
                for (int j = 0; j < 4; j++) {
                    sv[j] = __expf(sv[j] - nm);   // -inf -> 0
                    psum += sv[j];
                }
            }
            psum += __shfl_xor_sync(0xffffffffu, psum, 1);
            psum += __shfl_xor_sync(0xffffffffu, psum, 2);
            psum += __shfl_xor_sync(0xffffffffu, psum, 4);
            psum += __shfl_xor_sync(0xffffffffu, psum, 8);
            lI[i] = lI[i] * cf + psum;
            mI[i] = nm;
#pragma unroll
            for (int j = 0; j < 4; j++) accO[i][j] *= cf;
            *(float4*)(ps + (4 * ty + i) * 68 + 4 * tx) = make_float4(sv[0], sv[1], sv[2], sv[3]);
        }
        __syncthreads();

        // --- O += P V ---
#pragma unroll 4
        for (int mm = 0; mm < 64; mm++) {
            float4 bv = *(const float4*)(vs + mm * 68 + 4 * tx);
            float a0 = ps[(4 * ty + 0) * 68 + mm];
            float a1 = ps[(4 * ty + 1) * 68 + mm];
            float a2 = ps[(4 * ty + 2) * 68 + mm];
            float a3 = ps[(4 * ty + 3) * 68 + mm];
            accO[0][0] += a0 * bv.x; accO[0][1] += a0 * bv.y; accO[0][2] += a0 * bv.z; accO[0][3] += a0 * bv.w;
            accO[1][0] += a1 * bv.x; accO[1][1] += a1 * bv.y; accO[1][2] += a1 * bv.z; accO[1][3] += a1 * bv.w;
            accO[2][0] += a2 * bv.x; accO[2][1] += a2 * bv.y; accO[2][2] += a2 * bv.z; accO[2][3] += a2 * bv.w;
            accO[3][0] += a3 * bv.x; accO[3][1] += a3 * bv.y; accO[3][2] += a3 * bv.z; accO[3][3] += a3 * bv.w;
        }
        __syncthreads();
    }

    // normalize + write [b][n][h*64+dk]
#pragma unroll
    for (int i = 0; i < 4; i++) {
        float inv = 1.0f / lI[i];
        float4 o = make_float4(accO[i][0] * inv, accO[i][1] * inv, accO[i][2] * inv, accO[i][3] * inv);
        *(float4*)(g_o + ((size_t)b * NTOK + q0 + 4 * ty + i) * DM + h * DK + 4 * tx) = o;
    }
}

// ---------------------------------------------------------------------------
// Output projection: Y[i][c] = sum_d O[i][d] * out_w[c][d] + out_b[c]
// ---------------------------------------------------------------------------
__global__ __launch_bounds__(256) void outproj_kernel(
    const float* __restrict__ ow, const float* __restrict__ ob, float* __restrict__ out)
{
    __shared__ float AsT[32 * 68];   // [kk][row]
    __shared__ float Bs [32 * 68];   // [kk][col]  (= out_w transposed)

    const int tid = threadIdx.x;
    const int tx = tid & 15, ty = tid >> 4;
    const int c0 = blockIdx.x * 64;
    const int r0 = blockIdx.y * 64;

    float acc[4][4];
#pragma unroll
    for (int i = 0; i < 4; i++)
#pragma unroll
        for (int j = 0; j < 4; j++) acc[i][j] = 0.f;

    for (int k0 = 0; k0 < DM; k0 += 32) {
        {
            int r = tid >> 2, j = tid & 3;
            const float4* asrc = (const float4*)(g_o + (size_t)(r0 + r) * DM + k0 + j * 8);
#pragma unroll
            for (int p = 0; p < 2; p++) {
                float4 a4 = asrc[p];
                int d = j * 8 + p * 4;
                AsT[(d + 0) * 68 + r] = a4.x;
                AsT[(d + 1) * 68 + r] = a4.y;
                AsT[(d + 2) * 68 + r] = a4.z;
                AsT[(d + 3) * 68 + r] = a4.w;
            }
        }
        {
            int cc = tid >> 2, j = tid & 3;
            const float4* bsrc = (const float4*)(ow + (size_t)(c0 + cc) * DM + k0 + j * 8);
#pragma unroll
            for (int p = 0; p < 2; p++) {
                float4 w4 = bsrc[p];
                int d = j * 8 + p * 4;
                Bs[(d + 0) * 68 + cc] = w4.x;
                Bs[(d + 1) * 68 + cc] = w4.y;
                Bs[(d + 2) * 68 + cc] = w4.z;
                Bs[(d + 3) * 68 + cc] = w4.w;
            }
        }
        __syncthreads();
#pragma unroll
        for (int kk = 0; kk < 32; kk++) {
            float4 a = *(const float4*)(AsT + kk * 68 + 4 * ty);
            float4 b = *(const float4*)(Bs  + kk * 68 + 4 * tx);
            acc[0][0] += a.x * b.x; acc[0][1] += a.x * b.y; acc[0][2] += a.x * b.z; acc[0][3] += a.x * b.w;
            acc[1][0] += a.y * b.x; acc[1][1] += a.y * b.y; acc[1][2] += a.y * b.z; acc[1][3] += a.y * b.w;
            acc[2][0] += a.z * b.x; acc[2][1] += a.z * b.y; acc[2][2] += a.z * b.z; acc[2][3] += a.z * b.w;
            acc[3][0] += a.w * b.x; acc[3][1] += a.w * b.y; acc[3][2] += a.w * b.z; acc[3][3] += a.w * b.w;
        }
        __syncthreads();
    }

    float4 bias = *(const float4*)(ob + c0 + 4 * tx);
#pragma unroll
    for (int i = 0; i < 4; i++) {
        int row = r0 + 4 * ty + i;
        float4 o = make_float4(acc[i][0] + bias.x, acc[i][1] + bias.y,
                               acc[i][2] + bias.z, acc[i][3] + bias.w);
        *(float4*)(out + (size_t)row * DM + c0 + 4 * tx) = o;
    }
}

// ---------------------------------------------------------------------------
extern "C" void kernel_launch(void* const* d_in, const int* in_sizes, int n_in,
                              void* d_out, int out_size)
{
    const float* q      = (const float*)d_in[0];
    const float* k      = (const float*)d_in[1];
    const float* v      = (const float*)d_in[2];
    const float* coords = (const float*)d_in[3];
    const unsigned char* kpm = (const unsigned char*)d_in[4];
    const float* qp     = (const float*)d_in[5];
    const float* kpj    = (const float*)d_in[6];
    const float* vp     = (const float*)d_in[7];
    const float* ow     = (const float*)d_in[8];
    const float* ob     = (const float*)d_in[9];
    float* out = (float*)d_out;

    const int attn_smem = 17664 * 4;   // 70656 B
    cudaFuncSetAttribute(attn_kernel, cudaFuncAttributeMaxDynamicSharedMemorySize, attn_smem);

    proj_kernel<<<dim3(8, 64, 3), 256>>>(q, k, v, qp, kpj, vp);
    attn_kernel<<<dim3(NTOK / 64, NH, B_SZ), 256, attn_smem>>>(coords, kpm);
    outproj_kernel<<<dim3(8, 64), 256>>>(ow, ob, out);
}